// round 13
// baseline (speedup 1.0000x reference)
#include <cuda_runtime.h>
#include <math.h>
#include <float.h>

// ---------------------------------------------------------------------------
// EceLabelShift: equal-mass-bin ECE with label-shift weighting.
// R12: EVERYTHING in one persistent kernel (148 blocks x 1024 threads):
//   phase A: fused softmax/conf/argmax pass (grid-stride, warp per row)
//   phases 1-8: histogram quantiles -> edges -> bin stats -> final scalar,
//   separated by software grid barriers. Graph = memset + 1 kernel.
// ---------------------------------------------------------------------------

#define NC      100
#define NBINS   15
#define HSIZE   (1 << 18)            // conf in (0,1] -> bits>>12 < 0x40000
#define CHUNK   1024
#define NCHUNK  (HSIZE / CHUNK)      // 256
#define NRANK   32                   // 16 edges x (i, i+1) rank pairs
#define NMAX    500000
#define TB      148                  // blocks (<= SM count: all co-resident)
#define TT      1024                 // threads per block

struct ZeroBlock {
    unsigned hist[HSIZE];
    unsigned subhist[NRANK * 4096];
    double   wnum[NBINS];
    double   total;
    unsigned cnt[NBINS];
};
__device__ ZeroBlock gz;

__device__ float    g_conf_t[NMAX];
__device__ float    g_conf_s[NMAX];
__device__ float    g_wper[NMAX];
__device__ unsigned g_csum[NCHUNK];
__device__ int      g_rankBin[NRANK];
__device__ unsigned g_rankBase[NRANK];
__device__ float    g_srt[NRANK];
__device__ unsigned g_sync_cnt;      // monotonic grid-barrier ticket (never reset)

// --------------------------- grid barrier -----------------------------------
__device__ __forceinline__ void grid_sync() {
    __syncthreads();
    if (threadIdx.x == 0) {
        __threadfence();                                   // release my writes
        unsigned ticket = atomicAdd(&g_sync_cnt, 1u);
        unsigned target = (ticket / TB + 1u) * TB;
        unsigned v;
        do {
            asm volatile("ld.acquire.gpu.u32 %0, [%1];"
                         : "=r"(v) : "l"(&g_sync_cnt));
        } while (v < target);
    }
    __syncthreads();
}

// rank (0-indexed order statistic) needed for edge pair t: (i, i+1), clamped.
__device__ __forceinline__ long long rank_for(int t, int nt) {
    int k = t >> 1;
    double xq = (double)k * (double)nt / 15.0;
    long long i = (long long)floor(xq);
    if (i > (long long)nt - 1) i = (long long)nt - 1;
    long long r = i + (t & 1);
    if (r > (long long)nt - 1) r = (long long)nt - 1;
    return r;
}

// Inclusive block scan over 1024 threads (32 warps). All threads must call.
__device__ __forceinline__ unsigned blockScan1024(unsigned v, unsigned* sh) {
    int tid = threadIdx.x, lane = tid & 31, w = tid >> 5;
    unsigned sc = v;
#pragma unroll
    for (int o = 1; o < 32; o <<= 1) {
        unsigned u = __shfl_up_sync(0xffffffffu, sc, o);
        if (lane >= o) sc += u;
    }
    if (lane == 31) sh[w] = sc;
    __syncthreads();
    if (w == 0) {
        unsigned t = sh[lane];
#pragma unroll
        for (int o = 1; o < 32; o <<= 1) {
            unsigned u = __shfl_up_sync(0xffffffffu, t, o);
            if (lane >= o) t += u;
        }
        sh[lane] = t;
    }
    __syncthreads();
    return sc + (w ? sh[w - 1] : 0u);
}

__global__ void __launch_bounds__(TT, 1)
k_all(const float* __restrict__ lg_t, const float* __restrict__ lg_s,
      const void* __restrict__ labels, const float* __restrict__ wt,
      float* __restrict__ out, int nt, int ns) {
    __shared__ unsigned s_cpref[NCHUNK + 1];
    __shared__ unsigned s_sh[32];
    __shared__ int      s_cIdx;
    __shared__ int      s_first;
    __shared__ int      s_lab64;
    __shared__ float    s_e[16];
    __shared__ float    s_wn[NBINS];
    __shared__ unsigned s_ct[NBINS];
    __shared__ int      s_bins[NRANK];
    __shared__ double   s_ws[32];

    const int tid  = threadIdx.x;
    const int bid  = blockIdx.x;
    const int lane = tid & 31;
    const int wid  = tid >> 5;
    const int gstride = TB * TT;
    const int gtid    = bid * TT + tid;

    // ---- Phase 0 (per-block, no sync): labels dtype detect ----
    if (wid == 0) {
        const unsigned* lb = (const unsigned*)labels;
        unsigned v = lb[2 * lane + 1] | lb[2 * lane + 65];
        unsigned mask = __ballot_sync(0xffffffffu, v != 0u);
        if (lane == 0) s_lab64 = (mask == 0u) ? 1 : 0;
    }
    __syncthreads();
    const int lab64 = s_lab64;

    // ---- Phase A: fused conf pass, one warp per row, grid-stride ----
    {
        const int nWarps = TB * (TT / 32);
        int gwarp = bid * (TT / 32) + wid;
        int rows = nt + ns;
        for (int r = gwarp; r < rows; r += nWarps) {
            bool isT = r < nt;
            int row  = isT ? r : r - nt;
            const float4* p = (const float4*)((isT ? lg_t : lg_s) + (size_t)row * NC);
            float4 v;
            if (lane < 25) v = p[lane];
            else           v = make_float4(-FLT_MAX, -FLT_MAX, -FLT_MAX, -FLT_MAX);

            float m = fmaxf(fmaxf(v.x, v.y), fmaxf(v.z, v.w));
#pragma unroll
            for (int o = 16; o; o >>= 1) m = fmaxf(m, __shfl_xor_sync(0xffffffffu, m, o));

            float s = 0.0f;
            if (lane < 25)
                s = __expf(v.x - m) + __expf(v.y - m) + __expf(v.z - m) + __expf(v.w - m);
#pragma unroll
            for (int o = 16; o; o >>= 1) s += __shfl_xor_sync(0xffffffffu, s, o);

            if (isT) {
                if (lane == 0) {
                    float c = 1.0f / s;
                    g_conf_t[row] = c;
                    atomicAdd(&gz.hist[__float_as_uint(c) >> 12], 1u);
                }
            } else {
                int loc = 127;
                if (lane < 25) {
                    if (v.w == m) loc = 4 * lane + 3;
                    if (v.z == m) loc = 4 * lane + 2;
                    if (v.y == m) loc = 4 * lane + 1;
                    if (v.x == m) loc = 4 * lane;
                }
                unsigned mask = __ballot_sync(0xffffffffu, loc < 127);
                int src = __ffs(mask) - 1;
                int bi  = __shfl_sync(0xffffffffu, loc, src);
                if (lane == 0) {
                    g_conf_s[row] = 1.0f / s;
                    long long lab = lab64 ? ((const long long*)labels)[row]
                                          : (long long)((const int*)labels)[row];
                    g_wper[row] = (bi == (int)lab) ? wt[lab] : 0.0f;
                }
            }
        }
    }
    grid_sync();   // (1)

    // ---- Phase 1: per-chunk sums of coarse histogram ----
    for (int c = bid; c < NCHUNK; c += TB) {
        unsigned s = gz.hist[c * CHUNK + tid];
#pragma unroll
        for (int o = 16; o; o >>= 1) s += __shfl_xor_sync(0xffffffffu, s, o);
        if (lane == 0) s_sh[wid] = s;
        __syncthreads();
        if (wid == 0) {
            unsigned r2 = s_sh[lane];
#pragma unroll
            for (int o = 16; o; o >>= 1) r2 += __shfl_xor_sync(0xffffffffu, r2, o);
            if (lane == 0) g_csum[c] = r2;
        }
        __syncthreads();
    }
    grid_sync();   // (2)

    // ---- Phase 2: rank location (blocks 0..31) ----
    if (bid < NRANK) {
        if (tid == 0) s_first = 1 << 30;
        if (tid < 32) {
            unsigned pre[8]; unsigned run = 0;
#pragma unroll
            for (int j = 0; j < 8; j++) { unsigned h = g_csum[tid * 8 + j]; pre[j] = run; run += h; }
            unsigned sc = run;
#pragma unroll
            for (int o = 1; o < 32; o <<= 1) {
                unsigned u = __shfl_up_sync(0xffffffffu, sc, o);
                if (tid >= o) sc += u;
            }
            unsigned excl = sc - run;
#pragma unroll
            for (int j = 0; j < 8; j++) s_cpref[tid * 8 + j] = excl + pre[j];
            if (tid == 31) s_cpref[NCHUNK] = excl + run;
        }
        __syncthreads();
        unsigned r = (unsigned)rank_for(bid, nt);
        if (tid < NCHUNK && s_cpref[tid] <= r && r < s_cpref[tid + 1]) s_cIdx = tid;
        __syncthreads();
        int c = s_cIdx;
        unsigned h = gz.hist[c * CHUNK + tid];
        unsigned incl = blockScan1024(h, s_sh);
        unsigned cum0 = s_cpref[c];
        if (cum0 + incl > r) atomicMin(&s_first, tid);
        __syncthreads();
        if (tid == s_first) {
            g_rankBin[bid]  = c * CHUNK + tid;
            g_rankBase[bid] = cum0 + incl - h;
        }
    }
    grid_sync();   // (3)

    // ---- Phase 3: refine sub-histograms (all blocks) ----
    if (tid < NRANK) s_bins[tid] = g_rankBin[tid];
    __syncthreads();
    {
        int bmin = 0x7fffffff, bmax = -1;
#pragma unroll
        for (int t = 0; t < NRANK; t++) {
            int b = s_bins[t];
            bmin = min(bmin, b); bmax = max(bmax, b);
        }
        for (int i = gtid; i < nt; i += gstride) {
            unsigned key = __float_as_uint(g_conf_t[i]);
            int bbin = (int)(key >> 12);
            if (bbin < bmin || bbin > bmax) continue;
            unsigned low = key & 4095u;
#pragma unroll
            for (int t = 0; t < NRANK; t++)
                if (s_bins[t] == bbin) atomicAdd(&gz.subhist[t * 4096 + low], 1u);
        }
    }
    grid_sync();   // (4)

    // ---- Phase 4: select exact order statistics (blocks 0..31) ----
    if (bid < NRANK) {
        if (tid == 0) s_first = 1 << 30;
        __syncthreads();
        unsigned target = (unsigned)(rank_for(bid, nt) - (long long)g_rankBase[bid]);
        unsigned h[4], tsum = 0;
        const unsigned* hp = &gz.subhist[bid * 4096 + tid * 4];
#pragma unroll
        for (int j = 0; j < 4; j++) { h[j] = hp[j]; tsum += h[j]; }
        unsigned incl = blockScan1024(tsum, s_sh);
        unsigned cc = incl - tsum;
        int found = -1;
#pragma unroll
        for (int j = 0; j < 4; j++) {
            if (found < 0 && cc + h[j] > target) found = tid * 4 + j;
            cc += h[j];
        }
        if (found >= 0) atomicMin(&s_first, found);
        __syncthreads();
        if (tid == 0)
            g_srt[bid] = __uint_as_float(((unsigned)g_rankBin[bid] << 12) | (unsigned)s_first);
    }
    grid_sync();   // (5)

    // ---- Phase 5 (per-block, no extra sync): edges from order statistics ----
    if (tid < 16) {
        int k = tid; float e;
        if (k == 0)       e = g_srt[0];
        else if (k == 15) e = g_srt[31];
        else {
            double xq = (double)k * (double)nt / 15.0;
            long long i = (long long)floor(xq);
            double frac = xq - (double)i;
            double a = g_srt[2 * k], b2 = g_srt[2 * k + 1];
            e = (float)(a + frac * (b2 - a));
        }
        s_e[k] = e;
    }
    if (tid < NBINS) { s_wn[tid] = 0.0f; s_ct[tid] = 0u; }
    __syncthreads();

    // ---- Phase 6: bin accumulation (half the blocks source, half target) ----
    if (bid < TB / 2) {
        int stride = (TB / 2) * TT;
        for (int i = bid * TT + tid; i < ns; i += stride) {
            float w = g_wper[i];
            if (w != 0.0f) {
                float c = g_conf_s[i];
                if (c > s_e[0] && c <= s_e[15]) {
#pragma unroll
                    for (int b = 0; b < NBINS; b++)
                        if (c <= s_e[b + 1]) { atomicAdd(&s_wn[b], w); break; }
                }
            }
        }
    } else {
        int nb = TB - TB / 2;
        int stride = nb * TT;
        for (int i = (bid - TB / 2) * TT + tid; i < nt; i += stride) {
            float c = g_conf_t[i];
            if (c > s_e[0] && c <= s_e[15]) {
#pragma unroll
                for (int b = 0; b < NBINS; b++)
                    if (c <= s_e[b + 1]) { atomicAdd(&s_ct[b], 1u); break; }
            }
        }
    }
    __syncthreads();
    if (tid < NBINS) {
        if (s_wn[tid] != 0.0f) atomicAdd(&gz.wnum[tid], (double)s_wn[tid]);
        if (s_ct[tid])         atomicAdd(&gz.cnt[tid], s_ct[tid]);
    }
    grid_sync();   // (6)

    // ---- Phase 7 (per-block): cond_expect + ok flags, then diff sum ----
    {
        float ce[NBINS]; bool ok[NBINS];
        double normal = (double)(nt - 1) / (double)ns;
#pragma unroll
        for (int b = 0; b < NBINS; b++) {
            long long ct = (long long)gz.cnt[b];
            long long d  = ct - 1; if (d < 1) d = 1;
            ce[b] = (float)(normal * gz.wnum[b] / (double)d);
            ok[b] = (ct > 1);
        }
        double local = 0.0;
        for (int i = gtid; i < nt; i += gstride) {
            float c = g_conf_t[i];
            if (c > s_e[0] && c <= s_e[15]) {
#pragma unroll
                for (int b = 0; b < NBINS; b++)
                    if (c <= s_e[b + 1]) {
                        if (ok[b]) { float d = c - ce[b]; local += (double)d * (double)d; }
                        break;
                    }
            }
        }
#pragma unroll
        for (int o = 16; o; o >>= 1) local += __shfl_down_sync(0xffffffffu, local, o);
        if (lane == 0) s_ws[wid] = local;
        __syncthreads();
        if (wid == 0) {
            double v = s_ws[lane];
#pragma unroll
            for (int o = 16; o; o >>= 1) v += __shfl_down_sync(0xffffffffu, v, o);
            if (lane == 0) atomicAdd(&gz.total, v);
        }
    }
    grid_sync();   // (7)

    // ---- Phase 8: final scalar ----
    if (bid == 0 && tid == 0) out[0] = (float)(gz.total / (double)nt);
}

extern "C" void kernel_launch(void* const* d_in, const int* in_sizes, int n_in,
                              void* d_out, int out_size) {
    const float* lg_s = (const float*)d_in[0];
    const void*  lab  = d_in[1];
    const float* lg_t = (const float*)d_in[2];
    const float* wt   = (const float*)d_in[3];
    int ns = in_sizes[0] / NC;
    int nt = in_sizes[2] / NC;

    void* zp = nullptr;
    cudaGetSymbolAddress(&zp, gz);
    cudaMemsetAsync(zp, 0, sizeof(ZeroBlock), 0);

    k_all<<<TB, TT>>>(lg_t, lg_s, lab, wt, (float*)d_out, nt, ns);
    (void)n_in; (void)out_size;
}